// round 8
// baseline (speedup 1.0000x reference)
#include <cuda_runtime.h>
#include <cuda_bf16.h>
#include <cuda_fp8.h>
#include <cstdint>
#include <cstddef>

// Problem dims (fixed by the dataset)
#define M_TOTAL 8192
#define K_DIM   4096
#define N_DIM   16384
#define TILE_M  128
#define TILE_N  128
#define TILE_K  128                // fp8 elements = bytes per stage row
#define K_ITERS (K_DIM / TILE_K)   // 32
#define N_TILES (N_DIM / TILE_N)   // 128
#define M_TILES (M_TOTAL / TILE_M) // 64
#define THREADS 256                // 8 warps: 4(M) x 2(N), 32x64 per warp
#define STAGES  3
#define NORM_SPLIT 8
#define WSCALE 64.0f               // exact pow2: Wq = (W/norm)*64 ~ N(0,1)
#define INV_WSCALE (1.0f / 64.0f)

#define A_STAGE (TILE_M * TILE_K)                // 16384 B
#define B_STAGE (TILE_N * TILE_K)                // 16384 B
#define STAGE_BYTES (A_STAGE + B_STAGE)          // 32768
#define SMEM_TOTAL_GEMM (STAGES * STAGE_BYTES)   // 98304 (x2 CTAs = 192K/SM)

// -------- static device scratch (no allocations allowed) --------
__device__ float    d_norm_part[NORM_SPLIT * N_DIM];        // split-K partial sq-sums
__device__ float    d_norm_inv[N_DIM];
__device__ uint8_t  d_ga[(size_t)M_TOTAL * K_DIM];          // g in e4m3, [M,K] row-major
__device__ uint8_t  d_wt8[(size_t)N_DIM * K_DIM];           // 64*(W/norm)^T e4m3, [N,K]
__device__ float    d_partial[(size_t)N_TILES * M_TOTAL];   // partial LSE [n_tile][m]

// ------------------------- PTX helpers -------------------------
__device__ __forceinline__ uint32_t smem_u32(const void* p) {
    return (uint32_t)__cvta_generic_to_shared(p);
}
__device__ __forceinline__ void cp_async16(uint32_t smem, const void* gmem) {
    asm volatile("cp.async.cg.shared.global [%0], [%1], 16;" :: "r"(smem), "l"(gmem));
}
__device__ __forceinline__ void cp_commit() {
    asm volatile("cp.async.commit_group;" ::: "memory");
}
__device__ __forceinline__ void cp_wait1() {
    asm volatile("cp.async.wait_group 1;" ::: "memory");
}
__device__ __forceinline__ void ldsm_x4(uint32_t& r0, uint32_t& r1, uint32_t& r2, uint32_t& r3,
                                        uint32_t addr) {
    asm volatile("ldmatrix.sync.aligned.m8n8.x4.shared.b16 {%0,%1,%2,%3}, [%4];"
                 : "=r"(r0), "=r"(r1), "=r"(r2), "=r"(r3) : "r"(addr));
}
__device__ __forceinline__ void mma_fp8(float& d0, float& d1, float& d2, float& d3,
                                        uint32_t a0, uint32_t a1, uint32_t a2, uint32_t a3,
                                        uint32_t b0, uint32_t b1) {
    asm volatile(
        "mma.sync.aligned.m16n8k32.row.col.f32.e4m3.e4m3.f32 "
        "{%0,%1,%2,%3}, {%4,%5,%6,%7}, {%8,%9}, {%0,%1,%2,%3};"
        : "+f"(d0), "+f"(d1), "+f"(d2), "+f"(d3)
        : "r"(a0), "r"(a1), "r"(a2), "r"(a3), "r"(b0), "r"(b1));
}
__device__ __forceinline__ uint32_t swz(uint32_t byte_off) {
    return byte_off ^ ((byte_off >> 3) & 0x70);
}
// pack 4 floats -> 4 e4m3 bytes (byte0 = x ... byte3 = w)
__device__ __forceinline__ uint32_t pack_e4m3x4(float x, float y, float z, float w) {
    uint16_t lo, hi;
    asm("cvt.rn.satfinite.e4m3x2.f32 %0, %1, %2;" : "=h"(lo) : "f"(y), "f"(x));
    asm("cvt.rn.satfinite.e4m3x2.f32 %0, %1, %2;" : "=h"(hi) : "f"(w), "f"(z));
    return (uint32_t)lo | ((uint32_t)hi << 16);
}

// --------------------- prep kernels ---------------------

// 1) split-K partial column sq-sums, float4-vectorized
__global__ void norm_partial_kernel(const float4* __restrict__ W4) {
    int h4 = blockIdx.x * blockDim.x + threadIdx.x;
    int s = blockIdx.y;
    int k0 = s * (K_DIM / NORM_SPLIT);
    float4 acc = make_float4(0.f, 0.f, 0.f, 0.f);
#pragma unroll 4
    for (int k = k0; k < k0 + K_DIM / NORM_SPLIT; ++k) {
        float4 v = W4[(size_t)k * (N_DIM / 4) + h4];
        acc.x = fmaf(v.x, v.x, acc.x);
        acc.y = fmaf(v.y, v.y, acc.y);
        acc.z = fmaf(v.z, v.z, acc.z);
        acc.w = fmaf(v.w, v.w, acc.w);
    }
    reinterpret_cast<float4*>(d_norm_part)[(size_t)s * (N_DIM / 4) + h4] = acc;
}

// 1b) finalize: inv = WSCALE * rsqrt(sum of partials)
__global__ void norm_finalize_kernel() {
    int h = blockIdx.x * blockDim.x + threadIdx.x;
    float s = 0.f;
#pragma unroll
    for (int p = 0; p < NORM_SPLIT; ++p) s += d_norm_part[p * N_DIM + h];
    d_norm_inv[h] = WSCALE * rsqrtf(s);
}

// 2) Wt8[h][k] = e4m3(W[k][h] * 64 * norm_inv[h])  (tiled transpose, 4B stores)
__global__ void wt8_kernel(const float* __restrict__ W) {
    __shared__ float tile[32][33];   // [k_local][h_local]
    int h0 = blockIdx.x * 32;
    int k0 = blockIdx.y * 32;
    int tx = threadIdx.x, ty = threadIdx.y;  // (32, 8)
#pragma unroll
    for (int j = 0; j < 32; j += 8)
        tile[ty + j][tx] = W[(size_t)(k0 + ty + j) * N_DIM + h0 + tx];
    __syncthreads();
    int tid = ty * 32 + tx;          // 0..255
    int hl = tid >> 3;               // 0..31
    int kc = tid & 7;                // 0..7 (4 k each)
    int h = h0 + hl;
    float inv = d_norm_inv[h];
    uint32_t packed = pack_e4m3x4(tile[kc * 4 + 0][hl] * inv,
                                  tile[kc * 4 + 1][hl] * inv,
                                  tile[kc * 4 + 2][hl] * inv,
                                  tile[kc * 4 + 3][hl] * inv);
    *reinterpret_cast<uint32_t*>(d_wt8 + (size_t)h * K_DIM + k0 + kc * 4) = packed;
}

// 3) g -> e4m3
__global__ void ga_kernel(const float4* __restrict__ g, int n4) {
    int i = blockIdx.x * blockDim.x + threadIdx.x;
    if (i >= n4) return;
    float4 v = g[i];
    reinterpret_cast<uint32_t*>(d_ga)[i] = pack_e4m3x4(v.x, v.y, v.z, v.w);
}

// --------------------- fused GEMM + partial LSE ---------------------
// 256 threads = 8 warps in 4(M) x 2(N); each warp computes 32x64.
// fp8 m16n8k32; stage rows are 128B = K=128 fp8 -> 4 k32 chunks per stage.
// 2 CTAs/SM; raster x=m so a wave shares the same B band.

__global__ void __launch_bounds__(THREADS, 2) gemm_lse_kernel() {
    extern __shared__ char smem[];
    const uint32_t sb = smem_u32(smem);
    const int tid = threadIdx.x;
    const int wid = tid >> 5;
    const int lane = tid & 31;
    const int mw = wid & 3;        // warp M index (0..3)
    const int nw = wid >> 2;       // warp N index (0..1)
    const int m0 = blockIdx.x * TILE_M;
    const int n0 = blockIdx.y * TILE_N;

    const char* aBase = (const char*)d_ga + (size_t)m0 * K_DIM;
    const char* bBase = (const char*)d_wt8 + (size_t)n0 * K_DIM;

    auto load_stage = [&](int s, int it) {
        const uint32_t ab = sb + s * STAGE_BYTES;
        const uint32_t bb = ab + A_STAGE;
        const char* aK = aBase + it * TILE_K;
        const char* bK = bBase + it * TILE_K;
#pragma unroll
        for (int i = 0; i < A_STAGE / 16 / THREADS; ++i) {        // 4
            int idx = tid + i * THREADS;
            cp_async16(ab + swz((uint32_t)idx * 16),
                       aK + (size_t)(idx >> 3) * K_DIM + (idx & 7) * 16);
        }
#pragma unroll
        for (int i = 0; i < B_STAGE / 16 / THREADS; ++i) {        // 4
            int idx = tid + i * THREADS;
            cp_async16(bb + swz((uint32_t)idx * 16),
                       bK + (size_t)(idx >> 3) * K_DIM + (idx & 7) * 16);
        }
    };

    load_stage(0, 0); cp_commit();
    load_stage(1, 1); cp_commit();

    float acc[2][8][4];
#pragma unroll
    for (int t = 0; t < 2; ++t)
#pragma unroll
        for (int j = 0; j < 8; ++j)
#pragma unroll
            for (int c = 0; c < 4; ++c) acc[t][j][c] = 0.f;

    // ---- precomputed swizzled LDSM offsets; k-chunk applied via XOR ----
    const int a_row = lane & 15;          // row within m16 tile
    const int a_kh  = lane >> 4;          // 16B segment within 32B k-chunk
    const int b_row = lane & 7;
    const int b_grp = (lane >> 3) & 1;
    const int b_t2  = lane >> 4;
    uint32_t a_off[2], b_off[4];
#pragma unroll
    for (int t = 0; t < 2; ++t)
        a_off[t] = swz((uint32_t)(mw * 32 + t * 16 + a_row) * 128 + a_kh * 16);
#pragma unroll
    for (int p = 0; p < 4; ++p)
        b_off[p] = swz((uint32_t)(nw * 64 + p * 16 + b_t2 * 8 + b_row) * 128 + b_grp * 16);

    for (int it = 0; it < K_ITERS; ++it) {
        cp_wait1();
        __syncthreads();
        if (it + 2 < K_ITERS) load_stage((it + 2) % STAGES, it + 2);
        cp_commit();

        const uint32_t stageA = sb + (it % STAGES) * STAGE_BYTES;
        const uint32_t stageB = stageA + A_STAGE;

#pragma unroll
        for (int ks = 0; ks < 4; ++ks) {              // 4 k32 chunks
            const uint32_t kx = (uint32_t)(ks * 32);
            uint32_t a[2][4];
#pragma unroll
            for (int t = 0; t < 2; ++t)
                ldsm_x4(a[t][0], a[t][1], a[t][2], a[t][3], stageA + (a_off[t] ^ kx));
            uint32_t b[8][2];
#pragma unroll
            for (int p = 0; p < 4; ++p) {
                uint32_t r0, r1, r2, r3;
                ldsm_x4(r0, r1, r2, r3, stageB + (b_off[p] ^ kx));
                b[p * 2][0] = r0; b[p * 2][1] = r1;
                b[p * 2 + 1][0] = r2; b[p * 2 + 1][1] = r3;
            }
#pragma unroll
            for (int t = 0; t < 2; ++t)
#pragma unroll
                for (int j = 0; j < 8; ++j)
                    mma_fp8(acc[t][j][0], acc[t][j][1], acc[t][j][2], acc[t][j][3],
                            a[t][0], a[t][1], a[t][2], a[t][3], b[j][0], b[j][1]);
        }
    }

    __syncthreads();   // all warps done; reuse stage smem for reduction

    // ---- fused epilogue: per-row partial logsumexp over this tile's 128 cols ----
    // acc = 64 * hidsig; LSE in hidsig units: mx*(1/64) + log sum exp((a-mx)/64)
    float2* red = (float2*)smem;   // [2 n-warps][128 rows]
#pragma unroll
    for (int t = 0; t < 2; ++t) {
#pragma unroll
        for (int half = 0; half < 2; ++half) {
            float mx = -3.4e38f;
#pragma unroll
            for (int j = 0; j < 8; ++j) {
                mx = fmaxf(mx, acc[t][j][half * 2]);
                mx = fmaxf(mx, acc[t][j][half * 2 + 1]);
            }
            mx = fmaxf(mx, __shfl_xor_sync(0xFFFFFFFF, mx, 1));
            mx = fmaxf(mx, __shfl_xor_sync(0xFFFFFFFF, mx, 2));
            float s = 0.f;
#pragma unroll
            for (int j = 0; j < 8; ++j) {
                s += __expf((acc[t][j][half * 2] - mx) * INV_WSCALE);
                s += __expf((acc[t][j][half * 2 + 1] - mx) * INV_WSCALE);
            }
            s += __shfl_xor_sync(0xFFFFFFFF, s, 1);
            s += __shfl_xor_sync(0xFFFFFFFF, s, 2);
            if ((lane & 3) == 0) {
                int row = mw * 32 + t * 16 + half * 8 + (lane >> 2);
                red[nw * 128 + row] = make_float2(mx * INV_WSCALE, s);
            }
        }
    }
    __syncthreads();

    if (tid < TILE_M) {
        float2 v0 = red[tid], v1 = red[128 + tid];
        float m = fmaxf(v0.x, v1.x);
        float s = v0.y * __expf(v0.x - m) + v1.y * __expf(v1.x - m);
        d_partial[(size_t)blockIdx.y * M_TOTAL + m0 + tid] = m + __logf(s);
    }
}

// --------------------- final LSE combine ---------------------
__global__ void reduce_kernel(float* __restrict__ out) {
    int m = blockIdx.x * blockDim.x + threadIdx.x;
    if (m >= M_TOTAL) return;
    float mx = -3.4e38f;
#pragma unroll 8
    for (int j = 0; j < N_TILES; ++j)
        mx = fmaxf(mx, d_partial[(size_t)j * M_TOTAL + m]);
    float s = 0.f;
#pragma unroll 8
    for (int j = 0; j < N_TILES; ++j)
        s += __expf(d_partial[(size_t)j * M_TOTAL + m] - mx);
    out[m] = mx + logf(s);
}

// --------------------- launcher ---------------------
extern "C" void kernel_launch(void* const* d_in, const int* in_sizes, int n_in,
                              void* d_out, int out_size) {
    const float* g;
    const float* W;
    if (in_sizes[0] == M_TOTAL * K_DIM) {           // g first (expected metadata order)
        g = (const float*)d_in[0];
        W = (const float*)d_in[1];
    } else {
        g = (const float*)d_in[1];
        W = (const float*)d_in[0];
    }
    float* out = (float*)d_out;

    norm_partial_kernel<<<dim3(N_DIM / 4 / 256, NORM_SPLIT), 256>>>((const float4*)W);
    norm_finalize_kernel<<<N_DIM / 256, 256>>>();

    dim3 tb(32, 8);
    wt8_kernel<<<dim3(N_DIM / 32, K_DIM / 32), tb>>>(W);

    int n4 = (M_TOTAL * K_DIM) / 4;
    ga_kernel<<<(n4 + 255) / 256, 256>>>((const float4*)g, n4);

    cudaFuncSetAttribute(gemm_lse_kernel, cudaFuncAttributeMaxDynamicSharedMemorySize,
                         SMEM_TOTAL_GEMM);
    gemm_lse_kernel<<<dim3(M_TILES, N_TILES), THREADS, SMEM_TOTAL_GEMM>>>();

    reduce_kernel<<<(M_TOTAL + 255) / 256, 256>>>(out);
}

// round 9
// speedup vs baseline: 1.1246x; 1.1246x over previous
#include <cuda_runtime.h>
#include <cuda_bf16.h>
#include <cstdint>
#include <cstddef>

// Problem dims (fixed by the dataset)
#define M_TOTAL 8192
#define K_DIM   4096
#define N_DIM   16384
#define TILE_M  128
#define TILE_N  128
#define TILE_K  64
#define K_ITERS (K_DIM / TILE_K)   // 64
#define N_TILES (N_DIM / TILE_N)   // 128
#define M_TILES (M_TOTAL / TILE_M) // 64
#define THREADS 256                // 8 warps: 4(M) x 2(N), 32x64 per warp
#define STAGES  3
#define NORM_SPLIT 8

#define A_STAGE (TILE_M * TILE_K * 2)            // 16384 B
#define B_STAGE (TILE_N * TILE_K * 2)            // 16384 B
#define STAGE_BYTES (A_STAGE + B_STAGE)          // 32768
#define SMEM_TOTAL_GEMM (STAGES * STAGE_BYTES)   // 98304 (x2 CTAs = 192K/SM)

// -------- static device scratch (no allocations allowed) --------
__device__ float          d_norm_part[NORM_SPLIT * N_DIM];        // split-K partial sq-sums
__device__ float          d_norm_inv[N_DIM];
__device__ __nv_bfloat16  d_gb[(size_t)M_TOTAL * K_DIM];          // g in bf16, [M,K] row-major
__device__ __nv_bfloat16  d_wt[(size_t)N_DIM * K_DIM];            // (W/norm)^T bf16, [N,K] row-major
__device__ float          d_partial[(size_t)N_TILES * M_TOTAL];   // partial LSE [n_tile][m]

// ------------------------- PTX helpers -------------------------
__device__ __forceinline__ uint32_t smem_u32(const void* p) {
    return (uint32_t)__cvta_generic_to_shared(p);
}
__device__ __forceinline__ void cp_async16(uint32_t smem, const void* gmem) {
    asm volatile("cp.async.cg.shared.global [%0], [%1], 16;" :: "r"(smem), "l"(gmem));
}
__device__ __forceinline__ void mbar_init(uint32_t addr, uint32_t count) {
    asm volatile("mbarrier.init.shared.b64 [%0], %1;" :: "r"(addr), "r"(count) : "memory");
}
__device__ __forceinline__ void mbar_arrive(uint32_t addr) {
    asm volatile("mbarrier.arrive.shared.b64 _, [%0];" :: "r"(addr) : "memory");
}
// arrive on mbarrier when ALL prior cp.async of this thread have completed
__device__ __forceinline__ void cp_async_mbar_arrive(uint32_t addr) {
    asm volatile("cp.async.mbarrier.arrive.noinc.shared.b64 [%0];" :: "r"(addr) : "memory");
}
__device__ __forceinline__ void mbar_wait(uint32_t addr, uint32_t parity) {
    asm volatile(
        "{\n\t.reg .pred P1;\n\t"
        "WAIT_%=:\n\t"
        "mbarrier.try_wait.parity.acquire.cta.shared::cta.b64 P1, [%0], %1, 0x989680;\n\t"
        "@P1 bra DONE_%=;\n\t"
        "bra.uni WAIT_%=;\n\t"
        "DONE_%=:\n\t}"
        :: "r"(addr), "r"(parity) : "memory");
}
__device__ __forceinline__ void ldsm_x4(uint32_t& r0, uint32_t& r1, uint32_t& r2, uint32_t& r3,
                                        uint32_t addr) {
    asm volatile("ldmatrix.sync.aligned.m8n8.x4.shared.b16 {%0,%1,%2,%3}, [%4];"
                 : "=r"(r0), "=r"(r1), "=r"(r2), "=r"(r3) : "r"(addr));
}
__device__ __forceinline__ void mma_bf16(float& d0, float& d1, float& d2, float& d3,
                                         uint32_t a0, uint32_t a1, uint32_t a2, uint32_t a3,
                                         uint32_t b0, uint32_t b1) {
    asm volatile(
        "mma.sync.aligned.m16n8k16.row.col.f32.bf16.bf16.f32 "
        "{%0,%1,%2,%3}, {%4,%5,%6,%7}, {%8,%9}, {%0,%1,%2,%3};"
        : "+f"(d0), "+f"(d1), "+f"(d2), "+f"(d3)
        : "r"(a0), "r"(a1), "r"(a2), "r"(a3), "r"(b0), "r"(b1));
}
__device__ __forceinline__ uint32_t swz(uint32_t byte_off) {
    return byte_off ^ ((byte_off >> 3) & 0x70);
}

// --------------------- prep kernels ---------------------

// 1) split-K partial column sq-sums, float4-vectorized
__global__ void norm_partial_kernel(const float4* __restrict__ W4) {
    int h4 = blockIdx.x * blockDim.x + threadIdx.x;
    int s = blockIdx.y;
    int k0 = s * (K_DIM / NORM_SPLIT);
    float4 acc = make_float4(0.f, 0.f, 0.f, 0.f);
#pragma unroll 4
    for (int k = k0; k < k0 + K_DIM / NORM_SPLIT; ++k) {
        float4 v = W4[(size_t)k * (N_DIM / 4) + h4];
        acc.x = fmaf(v.x, v.x, acc.x);
        acc.y = fmaf(v.y, v.y, acc.y);
        acc.z = fmaf(v.z, v.z, acc.z);
        acc.w = fmaf(v.w, v.w, acc.w);
    }
    reinterpret_cast<float4*>(d_norm_part)[(size_t)s * (N_DIM / 4) + h4] = acc;
}

// 1b) finalize: inv = rsqrt(sum of partials)
__global__ void norm_finalize_kernel() {
    int h = blockIdx.x * blockDim.x + threadIdx.x;
    float s = 0.f;
#pragma unroll
    for (int p = 0; p < NORM_SPLIT; ++p) s += d_norm_part[p * N_DIM + h];
    d_norm_inv[h] = rsqrtf(s);
}

// 2) Wt[h][k] = bf16(W[k][h] * norm_inv[h])  (tiled transpose)
__global__ void wt_kernel(const float* __restrict__ W) {
    __shared__ float tile[32][33];
    int h0 = blockIdx.x * 32;
    int k0 = blockIdx.y * 32;
    int tx = threadIdx.x, ty = threadIdx.y;  // (32, 8)
#pragma unroll
    for (int j = 0; j < 32; j += 8)
        tile[ty + j][tx] = W[(size_t)(k0 + ty + j) * N_DIM + h0 + tx];
    __syncthreads();
#pragma unroll
    for (int j = 0; j < 32; j += 8) {
        int h = h0 + ty + j;
        d_wt[(size_t)h * K_DIM + k0 + tx] =
            __float2bfloat16(tile[tx][ty + j] * d_norm_inv[h]);
    }
}

// 3) g -> bf16
__global__ void gb_kernel(const float4* __restrict__ g, int n4) {
    int i = blockIdx.x * blockDim.x + threadIdx.x;
    if (i >= n4) return;
    float4 v = g[i];
    __nv_bfloat162* o = reinterpret_cast<__nv_bfloat162*>(d_gb) + (size_t)i * 2;
    o[0] = __floats2bfloat162_rn(v.x, v.y);
    o[1] = __floats2bfloat162_rn(v.z, v.w);
}

// --------------------- fused GEMM + partial LSE ---------------------
// 256 threads = 8 warps in 4(M) x 2(N); each warp computes 32x64. 2 CTAs/SM.
// Pipeline via per-stage mbarriers (cuda::pipeline pattern) instead of
// __syncthreads(): fast warps run ahead into the next stage, decorrelating
// the per-iteration LDSM bursts that starved the tensor pipe.

__global__ void __launch_bounds__(THREADS, 2) gemm_lse_kernel() {
    extern __shared__ char smem[];
    __shared__ __align__(8) uint64_t mbar_store[2 * STAGES];   // [full0..2, empty0..2]
    const uint32_t sb = smem_u32(smem);
    const uint32_t mb = smem_u32(mbar_store);
    const int tid = threadIdx.x;
    const int wid = tid >> 5;
    const int lane = tid & 31;
    const int mw = wid & 3;        // warp M index (0..3)
    const int nw = wid >> 2;       // warp N index (0..1)
    const int m0 = blockIdx.x * TILE_M;    // x = m tile (wave shares B band)
    const int n0 = blockIdx.y * TILE_N;

    auto full_bar  = [&](int s) { return mb + (uint32_t)s * 8; };
    auto empty_bar = [&](int s) { return mb + (uint32_t)(STAGES + s) * 8; };

    if (tid == 0) {
#pragma unroll
        for (int s = 0; s < STAGES; ++s) {
            mbar_init(full_bar(s), THREADS);   // one cp.async-arrive per thread
            mbar_init(empty_bar(s), THREADS);  // one arrive per thread after compute
        }
    }
    __syncthreads();

    const char* aBase = (const char*)d_gb + (size_t)m0 * (K_DIM * 2);
    const char* bBase = (const char*)d_wt + (size_t)n0 * (K_DIM * 2);

    auto load_stage = [&](int s, int it) {
        const uint32_t ab = sb + s * STAGE_BYTES;
        const uint32_t bb = ab + A_STAGE;
        const char* aK = aBase + it * (TILE_K * 2);
        const char* bK = bBase + it * (TILE_K * 2);
#pragma unroll
        for (int i = 0; i < A_STAGE / 16 / THREADS; ++i) {        // 4
            int idx = tid + i * THREADS;
            cp_async16(ab + swz((uint32_t)idx * 16),
                       aK + (size_t)(idx >> 3) * (K_DIM * 2) + (idx & 7) * 16);
        }
#pragma unroll
        for (int i = 0; i < B_STAGE / 16 / THREADS; ++i) {        // 4
            int idx = tid + i * THREADS;
            cp_async16(bb + swz((uint32_t)idx * 16),
                       bK + (size_t)(idx >> 3) * (K_DIM * 2) + (idx & 7) * 16);
        }
    };

    // Prologue: stages 0 and 1 (fresh slots, no empty wait).
    load_stage(0, 0); cp_async_mbar_arrive(full_bar(0));
    load_stage(1, 1); cp_async_mbar_arrive(full_bar(1));

    float acc[2][8][4];
#pragma unroll
    for (int t = 0; t < 2; ++t)
#pragma unroll
        for (int j = 0; j < 8; ++j)
#pragma unroll
            for (int c = 0; c < 4; ++c) acc[t][j][c] = 0.f;

    // ---- precomputed swizzled LDSM offsets; k-chunk applied via XOR ----
    const int a_row = lane & 15;
    const int a_kh  = lane >> 4;
    const int b_row = lane & 7;
    const int b_grp = (lane >> 3) & 1;
    const int b_t2  = lane >> 4;
    uint32_t a_off[2], b_off[4];
#pragma unroll
    for (int t = 0; t < 2; ++t)
        a_off[t] = swz((uint32_t)(mw * 32 + t * 16 + a_row) * 128 + a_kh * 16);
#pragma unroll
    for (int p = 0; p < 4; ++p)
        b_off[p] = swz((uint32_t)(nw * 64 + p * 16 + b_t2 * 8 + b_row) * 128 + b_grp * 16);

    for (int it = 0; it < K_ITERS; ++it) {
        const int s = it % STAGES;
        const uint32_t u = (uint32_t)(it / STAGES);
        mbar_wait(full_bar(s), u & 1);           // data ready (acquire)

        const uint32_t stageA = sb + s * STAGE_BYTES;
        const uint32_t stageB = stageA + A_STAGE;

#pragma unroll
        for (int ks = 0; ks < TILE_K / 16; ++ks) {    // 4 k16 steps
            const uint32_t kx = (uint32_t)(ks * 32);
            uint32_t a[2][4];
#pragma unroll
            for (int t = 0; t < 2; ++t)
                ldsm_x4(a[t][0], a[t][1], a[t][2], a[t][3], stageA + (a_off[t] ^ kx));
            uint32_t b[8][2];
#pragma unroll
            for (int p = 0; p < 4; ++p) {
                uint32_t r0, r1, r2, r3;
                ldsm_x4(r0, r1, r2, r3, stageB + (b_off[p] ^ kx));
                b[p * 2][0] = r0; b[p * 2][1] = r1;
                b[p * 2 + 1][0] = r2; b[p * 2 + 1][1] = r3;
            }
#pragma unroll
            for (int t = 0; t < 2; ++t)
#pragma unroll
                for (int j = 0; j < 8; ++j)
                    mma_bf16(acc[t][j][0], acc[t][j][1], acc[t][j][2], acc[t][j][3],
                             a[t][0], a[t][1], a[t][2], a[t][3], b[j][0], b[j][1]);
        }

        mbar_arrive(empty_bar(s));               // done reading stage s (release)

        const int L = it + 2;                    // next load, ring distance 2
        if (L < K_ITERS) {
            const int sl = L % STAGES;
            const uint32_t ul = (uint32_t)(L / STAGES);
            mbar_wait(empty_bar(sl), (ul & 1) ^ 1);  // slot free (first use passes)
            load_stage(sl, L);
            cp_async_mbar_arrive(full_bar(sl));
        }
    }

    __syncthreads();   // all warps done; reuse stage smem for reduction

    // ---- fused epilogue: per-row partial logsumexp over this tile's 128 cols ----
    float2* red = (float2*)smem;   // [2 n-warps][128 rows]
#pragma unroll
    for (int t = 0; t < 2; ++t) {
#pragma unroll
        for (int half = 0; half < 2; ++half) {
            float mx = -3.4e38f;
#pragma unroll
            for (int j = 0; j < 8; ++j) {
                mx = fmaxf(mx, acc[t][j][half * 2]);
                mx = fmaxf(mx, acc[t][j][half * 2 + 1]);
            }
            mx = fmaxf(mx, __shfl_xor_sync(0xFFFFFFFF, mx, 1));
            mx = fmaxf(mx, __shfl_xor_sync(0xFFFFFFFF, mx, 2));
            float s = 0.f;
#pragma unroll
            for (int j = 0; j < 8; ++j) {
                s += __expf(acc[t][j][half * 2] - mx);
                s += __expf(acc[t][j][half * 2 + 1] - mx);
            }
            s += __shfl_xor_sync(0xFFFFFFFF, s, 1);
            s += __shfl_xor_sync(0xFFFFFFFF, s, 2);
            if ((lane & 3) == 0) {
                int row = mw * 32 + t * 16 + half * 8 + (lane >> 2);
                red[nw * 128 + row] = make_float2(mx, s);
            }
        }
    }
    __syncthreads();

    if (tid < TILE_M) {
        float2 v0 = red[tid], v1 = red[128 + tid];
        float m = fmaxf(v0.x, v1.x);
        float s = v0.y * __expf(v0.x - m) + v1.y * __expf(v1.x - m);
        d_partial[(size_t)blockIdx.y * M_TOTAL + m0 + tid] = m + __logf(s);
    }
}

// --------------------- final LSE combine ---------------------
__global__ void reduce_kernel(float* __restrict__ out) {
    int m = blockIdx.x * blockDim.x + threadIdx.x;
    if (m >= M_TOTAL) return;
    float mx = -3.4e38f;
#pragma unroll 8
    for (int j = 0; j < N_TILES; ++j)
        mx = fmaxf(mx, d_partial[(size_t)j * M_TOTAL + m]);
    float s = 0.f;
#pragma unroll 8
    for (int j = 0; j < N_TILES; ++j)
        s += __expf(d_partial[(size_t)j * M_TOTAL + m] - mx);
    out[m] = mx + logf(s);
}

// --------------------- launcher ---------------------
extern "C" void kernel_launch(void* const* d_in, const int* in_sizes, int n_in,
                              void* d_out, int out_size) {
    const float* g;
    const float* W;
    if (in_sizes[0] == M_TOTAL * K_DIM) {           // g first (expected metadata order)
        g = (const float*)d_in[0];
        W = (const float*)d_in[1];
    } else {
        g = (const float*)d_in[1];
        W = (const float*)d_in[0];
    }
    float* out = (float*)d_out;

    norm_partial_kernel<<<dim3(N_DIM / 4 / 256, NORM_SPLIT), 256>>>((const float4*)W);
    norm_finalize_kernel<<<N_DIM / 256, 256>>>();

    dim3 tb(32, 8);
    wt_kernel<<<dim3(N_DIM / 32, K_DIM / 32), tb>>>(W);

    int n4 = (M_TOTAL * K_DIM) / 4;
    gb_kernel<<<(n4 + 255) / 256, 256>>>((const float4*)g, n4);

    cudaFuncSetAttribute(gemm_lse_kernel, cudaFuncAttributeMaxDynamicSharedMemorySize,
                         SMEM_TOTAL_GEMM);
    gemm_lse_kernel<<<dim3(M_TILES, N_TILES), THREADS, SMEM_TOTAL_GEMM>>>();

    reduce_kernel<<<(M_TOTAL + 255) / 256, 256>>>(out);
}

// round 10
// speedup vs baseline: 1.1402x; 1.0138x over previous
#include <cuda_runtime.h>
#include <cuda_bf16.h>
#include <cstdint>
#include <cstddef>

// Problem dims (fixed by the dataset)
#define M_TOTAL 8192
#define K_DIM   4096
#define N_DIM   16384
#define TILE_M  128
#define TILE_N  128
#define TILE_K  64
#define K_ITERS (K_DIM / TILE_K)   // 64
#define N_TILES (N_DIM / TILE_N)   // 128
#define M_TILES (M_TOTAL / TILE_M) // 64
#define THREADS 256                // 8 warps: 4(M) x 2(N), 32x64 per warp
#define STAGES  3
#define NORM_SPLIT 8

#define A_STAGE (TILE_M * TILE_K * 2)            // 16384 B
#define B_STAGE (TILE_N * TILE_K * 2)            // 16384 B
#define STAGE_BYTES (A_STAGE + B_STAGE)          // 32768
#define SMEM_TOTAL_GEMM (STAGES * STAGE_BYTES)   // 98304 (x2 CTAs = 192K/SM)

// -------- static device scratch (no allocations allowed) --------
__device__ float          d_norm_part[NORM_SPLIT * N_DIM];        // split-K partial sq-sums
__device__ float          d_norm_inv[N_DIM];
__device__ __nv_bfloat16  d_gb[(size_t)M_TOTAL * K_DIM];          // g in bf16, [M,K] row-major
__device__ __nv_bfloat16  d_wt[(size_t)N_DIM * K_DIM];            // (W/norm)^T bf16, [N,K] row-major
__device__ float          d_partial[(size_t)N_TILES * M_TOTAL];   // partial LSE [n_tile][m]

// ------------------------- PTX helpers -------------------------
__device__ __forceinline__ uint32_t smem_u32(const void* p) {
    return (uint32_t)__cvta_generic_to_shared(p);
}
__device__ __forceinline__ void cp_async16(uint32_t smem, const void* gmem) {
    asm volatile("cp.async.cg.shared.global [%0], [%1], 16;" :: "r"(smem), "l"(gmem));
}
__device__ __forceinline__ void cp_commit() {
    asm volatile("cp.async.commit_group;" ::: "memory");
}
__device__ __forceinline__ void cp_wait1() {
    asm volatile("cp.async.wait_group 1;" ::: "memory");
}
__device__ __forceinline__ void ldsm_x4(uint32_t& r0, uint32_t& r1, uint32_t& r2, uint32_t& r3,
                                        uint32_t addr) {
    asm volatile("ldmatrix.sync.aligned.m8n8.x4.shared.b16 {%0,%1,%2,%3}, [%4];"
                 : "=r"(r0), "=r"(r1), "=r"(r2), "=r"(r3) : "r"(addr));
}
__device__ __forceinline__ void mma_bf16(float& d0, float& d1, float& d2, float& d3,
                                         uint32_t a0, uint32_t a1, uint32_t a2, uint32_t a3,
                                         uint32_t b0, uint32_t b1) {
    asm volatile(
        "mma.sync.aligned.m16n8k16.row.col.f32.bf16.bf16.f32 "
        "{%0,%1,%2,%3}, {%4,%5,%6,%7}, {%8,%9}, {%0,%1,%2,%3};"
        : "+f"(d0), "+f"(d1), "+f"(d2), "+f"(d3)
        : "r"(a0), "r"(a1), "r"(a2), "r"(a3), "r"(b0), "r"(b1));
}
__device__ __forceinline__ uint32_t swz(uint32_t byte_off) {
    return byte_off ^ ((byte_off >> 3) & 0x70);
}

// --------------------- prep kernels ---------------------

// 1) split-K partial column sq-sums, float4-vectorized
__global__ void norm_partial_kernel(const float4* __restrict__ W4) {
    int h4 = blockIdx.x * blockDim.x + threadIdx.x;
    int s = blockIdx.y;
    int k0 = s * (K_DIM / NORM_SPLIT);
    float4 acc = make_float4(0.f, 0.f, 0.f, 0.f);
#pragma unroll 4
    for (int k = k0; k < k0 + K_DIM / NORM_SPLIT; ++k) {
        float4 v = W4[(size_t)k * (N_DIM / 4) + h4];
        acc.x = fmaf(v.x, v.x, acc.x);
        acc.y = fmaf(v.y, v.y, acc.y);
        acc.z = fmaf(v.z, v.z, acc.z);
        acc.w = fmaf(v.w, v.w, acc.w);
    }
    reinterpret_cast<float4*>(d_norm_part)[(size_t)s * (N_DIM / 4) + h4] = acc;
}

// 1b) finalize: inv = rsqrt(sum of partials)
__global__ void norm_finalize_kernel() {
    int h = blockIdx.x * blockDim.x + threadIdx.x;
    float s = 0.f;
#pragma unroll
    for (int p = 0; p < NORM_SPLIT; ++p) s += d_norm_part[p * N_DIM + h];
    d_norm_inv[h] = rsqrtf(s);
}

// 2) Wt[h][k] = bf16(W[k][h] * norm_inv[h])  (tiled transpose)
__global__ void wt_kernel(const float* __restrict__ W) {
    __shared__ float tile[32][33];
    int h0 = blockIdx.x * 32;
    int k0 = blockIdx.y * 32;
    int tx = threadIdx.x, ty = threadIdx.y;  // (32, 8)
#pragma unroll
    for (int j = 0; j < 32; j += 8)
        tile[ty + j][tx] = W[(size_t)(k0 + ty + j) * N_DIM + h0 + tx];
    __syncthreads();
#pragma unroll
    for (int j = 0; j < 32; j += 8) {
        int h = h0 + ty + j;
        d_wt[(size_t)h * K_DIM + k0 + tx] =
            __float2bfloat16(tile[tx][ty + j] * d_norm_inv[h]);
    }
}

// 3) g -> bf16
__global__ void gb_kernel(const float4* __restrict__ g, int n4) {
    int i = blockIdx.x * blockDim.x + threadIdx.x;
    if (i >= n4) return;
    float4 v = g[i];
    __nv_bfloat162* o = reinterpret_cast<__nv_bfloat162*>(d_gb) + (size_t)i * 2;
    o[0] = __floats2bfloat162_rn(v.x, v.y);
    o[1] = __floats2bfloat162_rn(v.z, v.w);
}

// --------------------- fused GEMM + partial LSE ---------------------
// 256 threads = 8 warps in 4(M) x 2(N); each warp computes 32x64. 2 CTAs/SM.
// Phase stagger: co-resident CTAs (bids ~148 apart at occupancy 2) are
// phase-locked — identical period, same start — so their barrier/LDSM-burst
// windows coincide and neither covers the other's stall. A one-time clock
// spin of ~half an iteration for wave-odd CTAs antialigns the pair (offset
// persists across waves since both CTAs of a pair finish together). The &3
// jitter spreads the chip-wide cp.async bursts (148 % 4 == 0, no cancel).

__global__ void __launch_bounds__(THREADS, 2) gemm_lse_kernel() {
    extern __shared__ char smem[];
    const uint32_t sb = smem_u32(smem);
    const int tid = threadIdx.x;
    const int wid = tid >> 5;
    const int lane = tid & 31;
    const int mw = wid & 3;        // warp M index (0..3)
    const int nw = wid >> 2;       // warp N index (0..1)
    const int m0 = blockIdx.x * TILE_M;    // x = m tile (wave shares B band)
    const int n0 = blockIdx.y * TILE_N;

    const char* aBase = (const char*)d_gb + (size_t)m0 * (K_DIM * 2);
    const char* bBase = (const char*)d_wt + (size_t)n0 * (K_DIM * 2);

    auto load_stage = [&](int s, int it) {
        const uint32_t ab = sb + s * STAGE_BYTES;
        const uint32_t bb = ab + A_STAGE;
        const char* aK = aBase + it * (TILE_K * 2);
        const char* bK = bBase + it * (TILE_K * 2);
#pragma unroll
        for (int i = 0; i < A_STAGE / 16 / THREADS; ++i) {        // 4
            int idx = tid + i * THREADS;
            cp_async16(ab + swz((uint32_t)idx * 16),
                       aK + (size_t)(idx >> 3) * (K_DIM * 2) + (idx & 7) * 16);
        }
#pragma unroll
        for (int i = 0; i < B_STAGE / 16 / THREADS; ++i) {        // 4
            int idx = tid + i * THREADS;
            cp_async16(bb + swz((uint32_t)idx * 16),
                       bK + (size_t)(idx >> 3) * (K_DIM * 2) + (idx & 7) * 16);
        }
    };

    load_stage(0, 0); cp_commit();
    load_stage(1, 1); cp_commit();

    // ---- phase stagger (loads above are already in flight during the spin) ----
    {
        int bid = blockIdx.x + (int)gridDim.x * blockIdx.y;
        unsigned int delay = (unsigned int)(((bid / 148) & 1) * 1100 + (bid & 3) * 150);
        if (delay) {
            unsigned long long t0 = clock64();
            while ((unsigned long long)(clock64() - t0) < delay) { }
        }
    }

    float acc[2][8][4];
#pragma unroll
    for (int t = 0; t < 2; ++t)
#pragma unroll
        for (int j = 0; j < 8; ++j)
#pragma unroll
            for (int c = 0; c < 4; ++c) acc[t][j][c] = 0.f;

    // ---- precomputed swizzled LDSM offsets; k-chunk applied via XOR ----
    const int a_row = lane & 15;
    const int a_kh  = lane >> 4;
    const int b_row = lane & 7;
    const int b_grp = (lane >> 3) & 1;
    const int b_t2  = lane >> 4;
    uint32_t a_off[2], b_off[4];
#pragma unroll
    for (int t = 0; t < 2; ++t)
        a_off[t] = swz((uint32_t)(mw * 32 + t * 16 + a_row) * 128 + a_kh * 16);
#pragma unroll
    for (int p = 0; p < 4; ++p)
        b_off[p] = swz((uint32_t)(nw * 64 + p * 16 + b_t2 * 8 + b_row) * 128 + b_grp * 16);

    for (int it = 0; it < K_ITERS; ++it) {
        cp_wait1();                 // stage `it` complete
        __syncthreads();
        if (it + 2 < K_ITERS) load_stage((it + 2) % STAGES, it + 2);
        cp_commit();

        const uint32_t stageA = sb + (it % STAGES) * STAGE_BYTES;
        const uint32_t stageB = stageA + A_STAGE;

#pragma unroll
        for (int ks = 0; ks < TILE_K / 16; ++ks) {    // 4 k16 steps
            const uint32_t kx = (uint32_t)(ks * 32);
            uint32_t a[2][4];
#pragma unroll
            for (int t = 0; t < 2; ++t)
                ldsm_x4(a[t][0], a[t][1], a[t][2], a[t][3], stageA + (a_off[t] ^ kx));
            uint32_t b[8][2];
#pragma unroll
            for (int p = 0; p < 4; ++p) {
                uint32_t r0, r1, r2, r3;
                ldsm_x4(r0, r1, r2, r3, stageB + (b_off[p] ^ kx));
                b[p * 2][0] = r0; b[p * 2][1] = r1;
                b[p * 2 + 1][0] = r2; b[p * 2 + 1][1] = r3;
            }
#pragma unroll
            for (int t = 0; t < 2; ++t)
#pragma unroll
                for (int j = 0; j < 8; ++j)
                    mma_bf16(acc[t][j][0], acc[t][j][1], acc[t][j][2], acc[t][j][3],
                             a[t][0], a[t][1], a[t][2], a[t][3], b[j][0], b[j][1]);
        }
    }

    __syncthreads();   // all warps done; reuse stage smem for reduction

    // ---- fused epilogue: per-row partial logsumexp over this tile's 128 cols ----
    float2* red = (float2*)smem;   // [2 n-warps][128 rows]
#pragma unroll
    for (int t = 0; t < 2; ++t) {
#pragma unroll
        for (int half = 0; half < 2; ++half) {
            float mx = -3.4e38f;
#pragma unroll
            for (int j = 0; j < 8; ++j) {
                mx = fmaxf(mx, acc[t][j][half * 2]);
                mx = fmaxf(mx, acc[t][j][half * 2 + 1]);
            }
            mx = fmaxf(mx, __shfl_xor_sync(0xFFFFFFFF, mx, 1));
            mx = fmaxf(mx, __shfl_xor_sync(0xFFFFFFFF, mx, 2));
            float s = 0.f;
#pragma unroll
            for (int j = 0; j < 8; ++j) {
                s += __expf(acc[t][j][half * 2] - mx);
                s += __expf(acc[t][j][half * 2 + 1] - mx);
            }
            s += __shfl_xor_sync(0xFFFFFFFF, s, 1);
            s += __shfl_xor_sync(0xFFFFFFFF, s, 2);
            if ((lane & 3) == 0) {
                int row = mw * 32 + t * 16 + half * 8 + (lane >> 2);
                red[nw * 128 + row] = make_float2(mx, s);
            }
        }
    }
    __syncthreads();

    if (tid < TILE_M) {
        float2 v0 = red[tid], v1 = red[128 + tid];
        float m = fmaxf(v0.x, v1.x);
        float s = v0.y * __expf(v0.x - m) + v1.y * __expf(v1.x - m);
        d_partial[(size_t)blockIdx.y * M_TOTAL + m0 + tid] = m + __logf(s);
    }
}

// --------------------- final LSE combine ---------------------
__global__ void reduce_kernel(float* __restrict__ out) {
    int m = blockIdx.x * blockDim.x + threadIdx.x;
    if (m >= M_TOTAL) return;
    float mx = -3.4e38f;
#pragma unroll 8
    for (int j = 0; j < N_TILES; ++j)
        mx = fmaxf(mx, d_partial[(size_t)j * M_TOTAL + m]);
    float s = 0.f;
#pragma unroll 8
    for (int j = 0; j < N_TILES; ++j)
        s += __expf(d_partial[(size_t)j * M_TOTAL + m] - mx);
    out[m] = mx + logf(s);
}

// --------------------- launcher ---------------------
extern "C" void kernel_launch(void* const* d_in, const int* in_sizes, int n_in,
                              void* d_out, int out_size) {
    const float* g;
    const float* W;
    if (in_sizes[0] == M_TOTAL * K_DIM) {           // g first (expected metadata order)
        g = (const float*)d_in[0];
        W = (const float*)d_in[1];
    } else {
        g = (const float*)d_in[1];
        W = (const float*)d_in[0];
    }
    float* out = (float*)d_out;

    norm_partial_kernel<<<dim3(N_DIM / 4 / 256, NORM_SPLIT), 256>>>((const float4*)W);
    norm_finalize_kernel<<<N_DIM / 256, 256>>>();

    dim3 tb(32, 8);
    wt_kernel<<<dim3(N_DIM / 32, K_DIM / 32), tb>>>(W);

    int n4 = (M_TOTAL * K_DIM) / 4;
    gb_kernel<<<(n4 + 255) / 256, 256>>>((const float4*)g, n4);

    cudaFuncSetAttribute(gemm_lse_kernel, cudaFuncAttributeMaxDynamicSharedMemorySize,
                         SMEM_TOTAL_GEMM);
    gemm_lse_kernel<<<dim3(M_TILES, N_TILES), THREADS, SMEM_TOTAL_GEMM>>>();

    reduce_kernel<<<(M_TOTAL + 255) / 256, 256>>>(out);
}